// round 3
// baseline (speedup 1.0000x reference)
#include <cuda_runtime.h>
#include <cuda_bf16.h>
#include <math.h>

#define NN 100000
#define EE 1250000
#define ET (NN + EE)          // edges + self loops
#define HH 64
#define CC 10

// -------- scratch (no allocations allowed) --------
__device__ float g_lin[NN * HH];     // GEMM output (pre-aggregation)
__device__ float g_agg[NN * HH];     // aggregation accumulator
__device__ float g_act[NN * HH];     // activated features
__device__ float g_deg[NN];
__device__ float g_dinv[NN];
__device__ float g_as[NN];
__device__ float g_ad[NN];
__device__ unsigned g_emax[NN];
__device__ float g_denom[NN];
__device__ float g_emb[HH];

// -------- helpers --------
__device__ __forceinline__ unsigned enc_f(float f) {
    int i = __float_as_int(f);
    return (i < 0) ? (unsigned)(~i) : ((unsigned)i | 0x80000000u);
}
__device__ __forceinline__ float dec_f(unsigned u) {
    int i = (u & 0x80000000u) ? (int)(u & 0x7fffffffu) : ~(int)u;
    return __int_as_float(i);
}

// -------- init / elementwise --------
__global__ void k_fill(float* p, float v, int n) {
    int i = blockIdx.x * blockDim.x + threadIdx.x;
    if (i < n) p[i] = v;
}
__global__ void k_zero4(float4* p, int n4) {
    int i = blockIdx.x * blockDim.x + threadIdx.x;
    if (i < n4) p[i] = make_float4(0.f, 0.f, 0.f, 0.f);
}
__global__ void k_gat_init(unsigned* emax, float* denom, int n) {
    int i = blockIdx.x * blockDim.x + threadIdx.x;
    if (i < n) { emax[i] = 0u; denom[i] = 0.f; }
}
__global__ void k_bias_relu(const float* __restrict__ in, const float* __restrict__ b,
                            float* __restrict__ out, int n) {
    int i = blockIdx.x * blockDim.x + threadIdx.x;
    if (i < n) out[i] = fmaxf(in[i] + b[i & 63], 0.f);
}
__global__ void k_dinv(const float* __restrict__ deg, float* __restrict__ dinv, int n) {
    int i = blockIdx.x * blockDim.x + threadIdx.x;
    if (i < n) dinv[i] = rsqrtf(deg[i]);   // deg >= 1 (self loop), matches rsqrt(max(deg,1e-12))
}

// -------- degree --------
__global__ void k_deg_count(const int* __restrict__ dst, float* deg, int e) {
    int i = blockIdx.x * blockDim.x + threadIdx.x;
    if (i < e) atomicAdd(&deg[dst[i]], 1.0f);
}

// -------- GEMM: C[M,64] = A[M,K] @ W[K,64] --------
template <int K>
__global__ void k_gemm(const float* __restrict__ A, const float* __restrict__ W,
                       float* __restrict__ C, int M) {
    __shared__ float Ws[K][64];
    __shared__ float Xs[K][65];
    int tid = threadIdx.x;
    for (int idx = tid; idx < K * 64; idx += 256) Ws[idx / 64][idx % 64] = W[idx];
    int base = blockIdx.x * 64;
    for (int idx = tid; idx < 64 * K; idx += 256) {
        int n = idx / K, k = idx - n * K;
        int row = base + n;
        Xs[k][n] = (row < M) ? A[row * K + k] : 0.f;
    }
    __syncthreads();
    int c0 = (tid & 15) * 4;
    int n0 = (tid >> 4) * 4;
    float acc[4][4];
#pragma unroll
    for (int i = 0; i < 4; i++)
#pragma unroll
        for (int j = 0; j < 4; j++) acc[i][j] = 0.f;
#pragma unroll
    for (int k = 0; k < K; k++) {
        float4 wv = *(const float4*)&Ws[k][c0];
        float x0 = Xs[k][n0 + 0], x1 = Xs[k][n0 + 1];
        float x2 = Xs[k][n0 + 2], x3 = Xs[k][n0 + 3];
        acc[0][0] += x0 * wv.x; acc[0][1] += x0 * wv.y; acc[0][2] += x0 * wv.z; acc[0][3] += x0 * wv.w;
        acc[1][0] += x1 * wv.x; acc[1][1] += x1 * wv.y; acc[1][2] += x1 * wv.z; acc[1][3] += x1 * wv.w;
        acc[2][0] += x2 * wv.x; acc[2][1] += x2 * wv.y; acc[2][2] += x2 * wv.z; acc[2][3] += x2 * wv.w;
        acc[3][0] += x3 * wv.x; acc[3][1] += x3 * wv.y; acc[3][2] += x3 * wv.z; acc[3][3] += x3 * wv.w;
    }
#pragma unroll
    for (int i = 0; i < 4; i++) {
        int row = base + n0 + i;
        if (row < M) {
            float4 o = make_float4(acc[i][0], acc[i][1], acc[i][2], acc[i][3]);
            *(float4*)&C[row * 64 + c0] = o;
        }
    }
}

// -------- GCN edge scatter: out[dst] += h[src] * dinv[src]*dinv[dst] --------
__global__ void k_gcn_scatter(const float4* __restrict__ h, float4* __restrict__ out,
                              const int* __restrict__ src, const int* __restrict__ dst,
                              const float* __restrict__ dinv) {
    int gt = blockIdx.x * blockDim.x + threadIdx.x;
    int e = gt >> 4, q = gt & 15;
    if (e >= ET) return;
    int s, d;
    if (e < EE) { s = src[e]; d = dst[e]; } else { s = d = e - EE; }
    float norm = dinv[s] * dinv[d];
    float4 v = h[s * 16 + q];
    v.x *= norm; v.y *= norm; v.z *= norm; v.w *= norm;
    atomicAdd(&out[d * 16 + q], v);
}

// -------- GAT node attention coefficients --------
__global__ void k_alpha(const float* __restrict__ h, const float* __restrict__ avs,
                        const float* __restrict__ avd, float* __restrict__ as_out,
                        float* __restrict__ ad_out, int n) {
    int warp = (blockIdx.x * blockDim.x + threadIdx.x) >> 5;
    int lane = threadIdx.x & 31;
    if (warp >= n) return;
    float h0 = h[warp * 64 + lane], h1 = h[warp * 64 + 32 + lane];
    float s = h0 * avs[lane] + h1 * avs[lane + 32];
    float d = h0 * avd[lane] + h1 * avd[lane + 32];
#pragma unroll
    for (int o = 16; o; o >>= 1) {
        s += __shfl_down_sync(0xffffffffu, s, o);
        d += __shfl_down_sync(0xffffffffu, d, o);
    }
    if (lane == 0) { as_out[warp] = s; ad_out[warp] = d; }
}

__device__ __forceinline__ float lrelu(float v) { return v >= 0.f ? v : 0.2f * v; }

__global__ void k_gat_max(const float* __restrict__ as_, const float* __restrict__ ad_,
                          const int* __restrict__ src, const int* __restrict__ dst,
                          unsigned* __restrict__ emax) {
    int e = blockIdx.x * blockDim.x + threadIdx.x;
    if (e >= ET) return;
    int s, d;
    if (e < EE) { s = src[e]; d = dst[e]; } else { s = d = e - EE; }
    float ev = lrelu(as_[s] + ad_[d]);
    atomicMax(&emax[d], enc_f(ev));
}

__global__ void k_gat_denom(const float* __restrict__ as_, const float* __restrict__ ad_,
                            const int* __restrict__ src, const int* __restrict__ dst,
                            const unsigned* __restrict__ emax, float* __restrict__ denom) {
    int e = blockIdx.x * blockDim.x + threadIdx.x;
    if (e >= ET) return;
    int s, d;
    if (e < EE) { s = src[e]; d = dst[e]; } else { s = d = e - EE; }
    float ev = lrelu(as_[s] + ad_[d]);
    float p = __expf(ev - dec_f(emax[d]));
    atomicAdd(&denom[d], p);
}

__global__ void k_gat_scatter(const float4* __restrict__ h, float4* __restrict__ out,
                              const float* __restrict__ as_, const float* __restrict__ ad_,
                              const int* __restrict__ src, const int* __restrict__ dst,
                              const unsigned* __restrict__ emax,
                              const float* __restrict__ denom) {
    int gt = blockIdx.x * blockDim.x + threadIdx.x;
    int e = gt >> 4, q = gt & 15;
    if (e >= ET) return;
    int s, d;
    if (e < EE) { s = src[e]; d = dst[e]; } else { s = d = e - EE; }
    float ev = lrelu(as_[s] + ad_[d]);
    float al = __expf(ev - dec_f(emax[d])) / denom[d];
    float4 v = h[s * 16 + q];
    v.x *= al; v.y *= al; v.z *= al; v.w *= al;
    atomicAdd(&out[d * 16 + q], v);
}

// -------- heads: optimizations + bottleneck --------
__global__ void k_heads(const float* __restrict__ h,
                        const float* __restrict__ Wopt, const float* __restrict__ bopt,
                        const float* __restrict__ Wb1, const float* __restrict__ bb1,
                        const float* __restrict__ Wb2, const float* __restrict__ bb2,
                        float* __restrict__ out, int n) {
    __shared__ float sWopt[640], sbopt[10], sWb1[2048], sbb1[32], sWb2[32];
    __shared__ float hrow[8][64];
    int tid = threadIdx.x;
    for (int i = tid; i < 640; i += 256) sWopt[i] = Wopt[i];
    for (int i = tid; i < 2048; i += 256) sWb1[i] = Wb1[i];
    if (tid < 10) sbopt[tid] = bopt[tid];
    if (tid < 32) { sbb1[tid] = bb1[tid]; sWb2[tid] = Wb2[tid]; }
    __syncthreads();
    float bb2v = bb2[0];
    int warp = tid >> 5, lane = tid & 31;
    for (int node = blockIdx.x * 8 + warp; node < n; node += gridDim.x * 8) {
        hrow[warp][lane] = h[node * 64 + lane];
        hrow[warp][lane + 32] = h[node * 64 + 32 + lane];
        __syncwarp();
        if (lane < CC) {
            float acc = sbopt[lane];
#pragma unroll
            for (int k = 0; k < 64; k++) acc += hrow[warp][k] * sWopt[k * CC + lane];
            out[node * CC + lane] = acc;
        }
        float t = sbb1[lane];
#pragma unroll
        for (int k = 0; k < 64; k++) t += hrow[warp][k] * sWb1[k * 32 + lane];
        t = fmaxf(t, 0.f) * sWb2[lane];
#pragma unroll
        for (int o = 16; o; o >>= 1) t += __shfl_down_sync(0xffffffffu, t, o);
        if (lane == 0) out[NN * CC + node] = 1.f / (1.f + __expf(-(t + bb2v)));
        __syncwarp();
    }
}

// -------- graph embedding (mean over nodes) --------
__global__ void k_emb_sum(const float* __restrict__ h, float* __restrict__ emb) {
    // grid 256 x block 256: stride 65536, divisible by 64 -> each thread sums one feature
    int g = blockIdx.x * 256 + threadIdx.x;
    float sum = 0.f;
    for (int idx = g; idx < NN * 64; idx += 65536) sum += h[idx];
    __shared__ float s[64];
    if (threadIdx.x < 64) s[threadIdx.x] = 0.f;
    __syncthreads();
    atomicAdd(&s[threadIdx.x & 63], sum);
    __syncthreads();
    if (threadIdx.x < 64) atomicAdd(&emb[threadIdx.x], s[threadIdx.x]);
}
__global__ void k_finish(const float* __restrict__ emb, float* __restrict__ out) {
    int t = threadIdx.x;
    if (t < 64) out[NN * CC + NN + t] = emb[t] * (1.0f / NN);
}

// -------- launch --------
extern "C" void kernel_launch(void* const* d_in, const int* in_sizes, int n_in,
                              void* d_out, int out_size) {
    const float* x    = (const float*)d_in[0];
    const int*   ei   = (const int*)d_in[1];
    const int*   src  = ei;
    const int*   dst  = ei + EE;
    const float* W1   = (const float*)d_in[2];
    const float* b1   = (const float*)d_in[3];
    const float* W2   = (const float*)d_in[4];
    const float* a_s  = (const float*)d_in[5];
    const float* a_d  = (const float*)d_in[6];
    const float* b2   = (const float*)d_in[7];
    const float* W3   = (const float*)d_in[8];
    const float* b3   = (const float*)d_in[9];
    const float* Wopt = (const float*)d_in[10];
    const float* bopt = (const float*)d_in[11];
    const float* Wb1  = (const float*)d_in[12];
    const float* bb1  = (const float*)d_in[13];
    const float* Wb2  = (const float*)d_in[14];
    const float* bb2  = (const float*)d_in[15];
    float* out = (float*)d_out;

    float *pLin, *pAgg, *pAct, *pDeg, *pDinv, *pAs, *pAd, *pDen, *pEmb;
    unsigned* pEmax;
    cudaGetSymbolAddress((void**)&pLin,  g_lin);
    cudaGetSymbolAddress((void**)&pAgg,  g_agg);
    cudaGetSymbolAddress((void**)&pAct,  g_act);
    cudaGetSymbolAddress((void**)&pDeg,  g_deg);
    cudaGetSymbolAddress((void**)&pDinv, g_dinv);
    cudaGetSymbolAddress((void**)&pAs,   g_as);
    cudaGetSymbolAddress((void**)&pAd,   g_ad);
    cudaGetSymbolAddress((void**)&pEmax, g_emax);
    cudaGetSymbolAddress((void**)&pDen,  g_denom);
    cudaGetSymbolAddress((void**)&pEmb,  g_emb);

    const int TB = 256;
    const int nBlkN   = (NN + TB - 1) / TB;                 // 391
    const int nBlkE   = (EE + TB - 1) / TB;                 // 4883
    const int nBlkEt  = (ET + TB - 1) / TB;                 // 5274
    const int nBlkSc  = (ET * 16 + TB - 1) / TB;            // 84375
    const int nBlkF4  = (NN * 16 + TB - 1) / TB;            // 6250 (N*64/4)
    const int nBlkEl  = (NN * 64 + TB - 1) / TB;            // 25000
    const int nBlkG   = (NN + 63) / 64;                     // 1563
    const int nBlkW   = (NN * 32 + TB - 1) / TB;            // 12500 (warp per node)

    // degree (self loop counted via init=1)
    k_fill<<<nBlkN, TB>>>(pDeg, 1.0f, NN);
    k_deg_count<<<nBlkE, TB>>>(dst, pDeg, EE);
    k_dinv<<<nBlkN, TB>>>(pDeg, pDinv, NN);

    // ---- GCN layer 1 ----
    k_gemm<32><<<nBlkG, TB>>>(x, W1, pLin, NN);
    k_zero4<<<nBlkF4, TB>>>((float4*)pAgg, NN * 16);
    k_gcn_scatter<<<nBlkSc, TB>>>((const float4*)pLin, (float4*)pAgg, src, dst, pDinv);
    k_bias_relu<<<nBlkEl, TB>>>(pAgg, b1, pAct, NN * 64);

    // ---- GAT layer ----
    k_gemm<64><<<nBlkG, TB>>>(pAct, W2, pLin, NN);
    k_alpha<<<nBlkW, TB>>>(pLin, a_s, a_d, pAs, pAd, NN);
    k_gat_init<<<nBlkN, TB>>>(pEmax, pDen, NN);
    k_gat_max<<<nBlkEt, TB>>>(pAs, pAd, src, dst, pEmax);
    k_gat_denom<<<nBlkEt, TB>>>(pAs, pAd, src, dst, pEmax, pDen);
    k_zero4<<<nBlkF4, TB>>>((float4*)pAgg, NN * 16);
    k_gat_scatter<<<nBlkSc, TB>>>((const float4*)pLin, (float4*)pAgg, pAs, pAd, src, dst, pEmax, pDen);
    k_bias_relu<<<nBlkEl, TB>>>(pAgg, b2, pAct, NN * 64);

    // ---- GCN layer 3 ----
    k_gemm<64><<<nBlkG, TB>>>(pAct, W3, pLin, NN);
    k_zero4<<<nBlkF4, TB>>>((float4*)pAgg, NN * 16);
    k_gcn_scatter<<<nBlkSc, TB>>>((const float4*)pLin, (float4*)pAgg, src, dst, pDinv);
    k_bias_relu<<<nBlkEl, TB>>>(pAgg, b3, pAct, NN * 64);

    // ---- heads + embedding ----
    k_heads<<<1184, TB>>>(pAct, Wopt, bopt, Wb1, bb1, Wb2, bb2, out, NN);
    k_fill<<<1, 64>>>(pEmb, 0.f, 64);
    k_emb_sum<<<256, 256>>>(pAct, pEmb);
    k_finish<<<1, 64>>>(pEmb, out);
}

// round 4
// speedup vs baseline: 1.0298x; 1.0298x over previous
#include <cuda_runtime.h>
#include <cuda_bf16.h>
#include <math.h>

#define NN 100000
#define EE 1250000
#define ET (NN + EE)          // edges + self loops
#define CC 10

// -------- scratch (no allocations allowed) --------
__device__ float g_lin[NN * 64];     // GEMM output (pre-aggregation)
__device__ float g_act[NN * 64];     // activated features
__device__ int   g_deg[NN];
__device__ int   g_rowptr[NN + 1];
__device__ int   g_cursor[NN];
__device__ int   g_csr[ET];          // src node per CSR slot (bucketed by dst)
__device__ float g_dinv[NN];
__device__ float g_as[NN];
__device__ float g_ad[NN];
__device__ float g_emb[64];

// ======== CSR build ========
__global__ void k_deg_init(int* deg) {
    int i = blockIdx.x * blockDim.x + threadIdx.x;
    if (i < NN) deg[i] = 1;                    // self loop
}
__global__ void k_deg_count(const int* __restrict__ dst, int* deg) {
    int e = blockIdx.x * blockDim.x + threadIdx.x;
    if (e < EE) atomicAdd(&deg[dst[e]], 1);
}
// single-block scan: row_ptr (exclusive), cursor copy, dinv
__global__ void k_scan(const int* __restrict__ deg, int* __restrict__ rp,
                       int* __restrict__ cur, float* __restrict__ dinv) {
    __shared__ int ssum[1024];
    int t = threadIdx.x;
    const int CH = (NN + 1023) / 1024;         // 98
    int b0 = t * CH;
    int e0 = min(b0 + CH, NN);
    int s = 0;
    for (int i = b0; i < e0; i++) s += deg[i];
    ssum[t] = s;
    __syncthreads();
    for (int off = 1; off < 1024; off <<= 1) {
        int u = (t >= off) ? ssum[t - off] : 0;
        __syncthreads();
        ssum[t] += u;
        __syncthreads();
    }
    int run = ssum[t] - s;                     // exclusive prefix of this chunk
    for (int i = b0; i < e0; i++) {
        int d = deg[i];
        rp[i] = run;
        cur[i] = run;
        dinv[i] = rsqrtf((float)d);
        run += d;
    }
    if (t == 1023) rp[NN] = ssum[1023];
}
__global__ void k_csr_fill(const int* __restrict__ src, const int* __restrict__ dst,
                           int* __restrict__ cur, int* __restrict__ csr) {
    int i = blockIdx.x * blockDim.x + threadIdx.x;
    if (i >= ET) return;
    int s, d;
    if (i < EE) { s = src[i]; d = dst[i]; } else { s = d = i - EE; }
    int pos = atomicAdd(&cur[d], 1);
    csr[pos] = s;
}

// ======== GEMM: C[M,64] = A[M,K] @ W[K,64] ========
template <int K>
__global__ void k_gemm(const float* __restrict__ A, const float* __restrict__ W,
                       float* __restrict__ C, int M) {
    __shared__ float Ws[K][64];
    __shared__ float Xs[K][68];                // 68: 16B-aligned float4 rows
    int tid = threadIdx.x;
    for (int idx = tid; idx < K * 64; idx += 256) Ws[idx / 64][idx % 64] = W[idx];
    int base = blockIdx.x * 64;
    for (int idx = tid; idx < 64 * K; idx += 256) {
        int n = idx / K, k = idx - n * K;
        int row = base + n;
        Xs[k][n] = (row < M) ? A[row * K + k] : 0.f;
    }
    __syncthreads();
    int c0 = (tid & 15) * 4;
    int n0 = (tid >> 4) * 4;
    float acc[4][4];
#pragma unroll
    for (int i = 0; i < 4; i++)
#pragma unroll
        for (int j = 0; j < 4; j++) acc[i][j] = 0.f;
#pragma unroll
    for (int k = 0; k < K; k++) {
        float4 wv = *(const float4*)&Ws[k][c0];
        float4 xv = *(const float4*)&Xs[k][n0];
        acc[0][0] += xv.x * wv.x; acc[0][1] += xv.x * wv.y; acc[0][2] += xv.x * wv.z; acc[0][3] += xv.x * wv.w;
        acc[1][0] += xv.y * wv.x; acc[1][1] += xv.y * wv.y; acc[1][2] += xv.y * wv.z; acc[1][3] += xv.y * wv.w;
        acc[2][0] += xv.z * wv.x; acc[2][1] += xv.z * wv.y; acc[2][2] += xv.z * wv.z; acc[2][3] += xv.z * wv.w;
        acc[3][0] += xv.w * wv.x; acc[3][1] += xv.w * wv.y; acc[3][2] += xv.w * wv.z; acc[3][3] += xv.w * wv.w;
    }
#pragma unroll
    for (int i = 0; i < 4; i++) {
        int row = base + n0 + i;
        if (row < M) {
            float4 o = make_float4(acc[i][0], acc[i][1], acc[i][2], acc[i][3]);
            *(float4*)&C[row * 64 + c0] = o;
        }
    }
}

// ======== GCN aggregation (CSR gather, warp per dst node) + bias + relu ========
__global__ void k_gcn_agg(const float* __restrict__ h, const int* __restrict__ rp,
                          const int* __restrict__ csr, const float* __restrict__ dinv,
                          const float* __restrict__ b, float* __restrict__ act) {
    int node = blockIdx.x * 8 + (threadIdx.x >> 5);
    if (node >= NN) return;
    int lane = threadIdx.x & 31;
    int e = rp[node], end = rp[node + 1];
    float dd = dinv[node];
    float a0 = 0.f, a1 = 0.f;
    for (; e + 2 <= end; e += 2) {
        int s0 = csr[e], s1 = csr[e + 1];
        float m0 = dinv[s0] * dd, m1 = dinv[s1] * dd;
        float h00 = h[s0 * 64 + lane],      h01 = h[s0 * 64 + 32 + lane];
        float h10 = h[s1 * 64 + lane],      h11 = h[s1 * 64 + 32 + lane];
        a0 = fmaf(h00, m0, a0); a1 = fmaf(h01, m0, a1);
        a0 = fmaf(h10, m1, a0); a1 = fmaf(h11, m1, a1);
    }
    if (e < end) {
        int s = csr[e];
        float m = dinv[s] * dd;
        a0 = fmaf(h[s * 64 + lane], m, a0);
        a1 = fmaf(h[s * 64 + 32 + lane], m, a1);
    }
    act[node * 64 + lane]      = fmaxf(a0 + b[lane], 0.f);
    act[node * 64 + 32 + lane] = fmaxf(a1 + b[lane + 32], 0.f);
}

// ======== GAT node attention coefficients ========
__global__ void k_alpha(const float* __restrict__ h, const float* __restrict__ avs,
                        const float* __restrict__ avd, float* __restrict__ as_out,
                        float* __restrict__ ad_out, int n) {
    int warp = (blockIdx.x * blockDim.x + threadIdx.x) >> 5;
    int lane = threadIdx.x & 31;
    if (warp >= n) return;
    float h0 = h[warp * 64 + lane], h1 = h[warp * 64 + 32 + lane];
    float s = h0 * avs[lane] + h1 * avs[lane + 32];
    float d = h0 * avd[lane] + h1 * avd[lane + 32];
#pragma unroll
    for (int o = 16; o; o >>= 1) {
        s += __shfl_down_sync(0xffffffffu, s, o);
        d += __shfl_down_sync(0xffffffffu, d, o);
    }
    if (lane == 0) { as_out[warp] = s; ad_out[warp] = d; }
}

__device__ __forceinline__ float lrelu(float v) { return v >= 0.f ? v : 0.2f * v; }

// ======== fused GAT aggregation: softmax over incoming edges + gather ========
__global__ void k_gat_agg(const float* __restrict__ h, const int* __restrict__ rp,
                          const int* __restrict__ csr, const float* __restrict__ as_,
                          const float* __restrict__ ad_, const float* __restrict__ b,
                          float* __restrict__ act) {
    int node = blockIdx.x * 8 + (threadIdx.x >> 5);
    if (node >= NN) return;
    int lane = threadIdx.x & 31;
    int begin = rp[node], end = rp[node + 1];
    float adv = ad_[node];

    // pass 1: max over edges (lanes strided over edges)
    float mx = -1e30f;
    for (int e = begin + lane; e < end; e += 32)
        mx = fmaxf(mx, lrelu(as_[csr[e]] + adv));
#pragma unroll
    for (int o = 16; o; o >>= 1) mx = fmaxf(mx, __shfl_xor_sync(0xffffffffu, mx, o));

    // pass 2: denom
    float sm = 0.f;
    for (int e = begin + lane; e < end; e += 32)
        sm += __expf(lrelu(as_[csr[e]] + adv) - mx);
#pragma unroll
    for (int o = 16; o; o >>= 1) sm += __shfl_xor_sync(0xffffffffu, sm, o);
    float inv = 1.f / sm;

    // pass 3: weighted feature gather (all lanes per edge, lanes = features)
    float a0 = 0.f, a1 = 0.f;
    int e = begin;
    for (; e + 2 <= end; e += 2) {
        int s0 = csr[e], s1 = csr[e + 1];
        float al0 = __expf(lrelu(as_[s0] + adv) - mx) * inv;
        float al1 = __expf(lrelu(as_[s1] + adv) - mx) * inv;
        float h00 = h[s0 * 64 + lane], h01 = h[s0 * 64 + 32 + lane];
        float h10 = h[s1 * 64 + lane], h11 = h[s1 * 64 + 32 + lane];
        a0 = fmaf(h00, al0, a0); a1 = fmaf(h01, al0, a1);
        a0 = fmaf(h10, al1, a0); a1 = fmaf(h11, al1, a1);
    }
    if (e < end) {
        int s = csr[e];
        float al = __expf(lrelu(as_[s] + adv) - mx) * inv;
        a0 = fmaf(h[s * 64 + lane], al, a0);
        a1 = fmaf(h[s * 64 + 32 + lane], al, a1);
    }
    act[node * 64 + lane]      = fmaxf(a0 + b[lane], 0.f);
    act[node * 64 + 32 + lane] = fmaxf(a1 + b[lane + 32], 0.f);
}

// ======== heads: optimizations + bottleneck ========
__global__ void k_heads(const float* __restrict__ h,
                        const float* __restrict__ Wopt, const float* __restrict__ bopt,
                        const float* __restrict__ Wb1, const float* __restrict__ bb1,
                        const float* __restrict__ Wb2, const float* __restrict__ bb2,
                        float* __restrict__ out, int n) {
    __shared__ float sWopt[640], sbopt[10], sWb1[2048], sbb1[32], sWb2[32];
    __shared__ float hrow[8][64];
    int tid = threadIdx.x;
    for (int i = tid; i < 640; i += 256) sWopt[i] = Wopt[i];
    for (int i = tid; i < 2048; i += 256) sWb1[i] = Wb1[i];
    if (tid < 10) sbopt[tid] = bopt[tid];
    if (tid < 32) { sbb1[tid] = bb1[tid]; sWb2[tid] = Wb2[tid]; }
    __syncthreads();
    float bb2v = bb2[0];
    int warp = tid >> 5, lane = tid & 31;
    for (int node = blockIdx.x * 8 + warp; node < n; node += gridDim.x * 8) {
        hrow[warp][lane] = h[node * 64 + lane];
        hrow[warp][lane + 32] = h[node * 64 + 32 + lane];
        __syncwarp();
        if (lane < CC) {
            float acc = sbopt[lane];
#pragma unroll
            for (int k = 0; k < 64; k++) acc += hrow[warp][k] * sWopt[k * CC + lane];
            out[node * CC + lane] = acc;
        }
        float t = sbb1[lane];
#pragma unroll
        for (int k = 0; k < 64; k++) t += hrow[warp][k] * sWb1[k * 32 + lane];
        t = fmaxf(t, 0.f) * sWb2[lane];
#pragma unroll
        for (int o = 16; o; o >>= 1) t += __shfl_down_sync(0xffffffffu, t, o);
        if (lane == 0) out[NN * CC + node] = 1.f / (1.f + __expf(-(t + bb2v)));
        __syncwarp();
    }
}

// ======== graph embedding (mean over nodes) ========
__global__ void k_fill(float* p, float v, int n) {
    int i = blockIdx.x * blockDim.x + threadIdx.x;
    if (i < n) p[i] = v;
}
__global__ void k_emb_sum(const float* __restrict__ h, float* __restrict__ emb) {
    int g = blockIdx.x * 256 + threadIdx.x;
    float sum = 0.f;
    for (int idx = g; idx < NN * 64; idx += 65536) sum += h[idx];
    __shared__ float s[64];
    if (threadIdx.x < 64) s[threadIdx.x] = 0.f;
    __syncthreads();
    atomicAdd(&s[threadIdx.x & 63], sum);
    __syncthreads();
    if (threadIdx.x < 64) atomicAdd(&emb[threadIdx.x], s[threadIdx.x]);
}
__global__ void k_finish(const float* __restrict__ emb, float* __restrict__ out) {
    int t = threadIdx.x;
    if (t < 64) out[NN * CC + NN + t] = emb[t] * (1.0f / NN);
}

// ======== launch ========
extern "C" void kernel_launch(void* const* d_in, const int* in_sizes, int n_in,
                              void* d_out, int out_size) {
    const float* x    = (const float*)d_in[0];
    const int*   ei   = (const int*)d_in[1];
    const int*   src  = ei;
    const int*   dst  = ei + EE;
    const float* W1   = (const float*)d_in[2];
    const float* b1   = (const float*)d_in[3];
    const float* W2   = (const float*)d_in[4];
    const float* a_s  = (const float*)d_in[5];
    const float* a_d  = (const float*)d_in[6];
    const float* b2   = (const float*)d_in[7];
    const float* W3   = (const float*)d_in[8];
    const float* b3   = (const float*)d_in[9];
    const float* Wopt = (const float*)d_in[10];
    const float* bopt = (const float*)d_in[11];
    const float* Wb1  = (const float*)d_in[12];
    const float* bb1  = (const float*)d_in[13];
    const float* Wb2  = (const float*)d_in[14];
    const float* bb2  = (const float*)d_in[15];
    float* out = (float*)d_out;

    float *pLin, *pAct, *pDinv, *pAs, *pAd, *pEmb;
    int *pDeg, *pRp, *pCur, *pCsr;
    cudaGetSymbolAddress((void**)&pLin,  g_lin);
    cudaGetSymbolAddress((void**)&pAct,  g_act);
    cudaGetSymbolAddress((void**)&pDeg,  g_deg);
    cudaGetSymbolAddress((void**)&pRp,   g_rowptr);
    cudaGetSymbolAddress((void**)&pCur,  g_cursor);
    cudaGetSymbolAddress((void**)&pCsr,  g_csr);
    cudaGetSymbolAddress((void**)&pDinv, g_dinv);
    cudaGetSymbolAddress((void**)&pAs,   g_as);
    cudaGetSymbolAddress((void**)&pAd,   g_ad);
    cudaGetSymbolAddress((void**)&pEmb,  g_emb);

    const int TB = 256;
    const int nBlkN  = (NN + TB - 1) / TB;
    const int nBlkE  = (EE + TB - 1) / TB;
    const int nBlkEt = (ET + TB - 1) / TB;
    const int nBlkG  = (NN + 63) / 64;
    const int nBlkW  = (NN * 32 + TB - 1) / TB;
    const int nBlkA  = (NN + 7) / 8;           // warp per node

    // ---- CSR build (once, reused by all 3 layers) ----
    k_deg_init<<<nBlkN, TB>>>(pDeg);
    k_deg_count<<<nBlkE, TB>>>(dst, pDeg);
    k_scan<<<1, 1024>>>(pDeg, pRp, pCur, pDinv);
    k_csr_fill<<<nBlkEt, TB>>>(src, dst, pCur, pCsr);

    // ---- GCN layer 1 ----
    k_gemm<32><<<nBlkG, TB>>>(x, W1, pLin, NN);
    k_gcn_agg<<<nBlkA, TB>>>(pLin, pRp, pCsr, pDinv, b1, pAct);

    // ---- GAT layer ----
    k_gemm<64><<<nBlkG, TB>>>(pAct, W2, pLin, NN);
    k_alpha<<<nBlkW, TB>>>(pLin, a_s, a_d, pAs, pAd, NN);
    k_gat_agg<<<nBlkA, TB>>>(pLin, pRp, pCsr, pAs, pAd, b2, pAct);

    // ---- GCN layer 3 ----
    k_gemm<64><<<nBlkG, TB>>>(pAct, W3, pLin, NN);
    k_gcn_agg<<<nBlkA, TB>>>(pLin, pRp, pCsr, pDinv, b3, pAct);

    // ---- heads + embedding ----
    k_heads<<<1184, TB>>>(pAct, Wopt, bopt, Wb1, bb1, Wb2, bb2, out, NN);
    k_fill<<<1, 64>>>(pEmb, 0.f, 64);
    k_emb_sum<<<256, 256>>>(pAct, pEmb);
    k_finish<<<1, 64>>>(pEmb, out);
}

// round 5
// speedup vs baseline: 1.5684x; 1.5230x over previous
#include <cuda_runtime.h>
#include <cuda_bf16.h>
#include <math.h>

#define NN 100000
#define EE 1250000
#define ET (NN + EE)          // edges + self loops
#define CC 10
#define NB 391                // ceil(NN/256)

// -------- scratch (no allocations allowed) --------
__device__ float g_lin[NN * 64];
__device__ float g_act[NN * 64];
__device__ int   g_deg[NN];
__device__ int   g_rowptr[NN + 1];
__device__ int   g_cursor[NN];
__device__ int   g_csr[ET];
__device__ int   g_bsum[512];
__device__ int   g_bbase[512];
__device__ float g_dinv[NN];
__device__ float g_as[NN];
__device__ float g_ad[NN];
__device__ float g_emb[64];

// ======== f32x2 packed math helpers (sm_103a FFMA2) ========
__device__ __forceinline__ unsigned long long pk2(float a, float b) {
    unsigned long long r;
    asm("mov.b64 %0,{%1,%2};" : "=l"(r) : "f"(a), "f"(b));
    return r;
}
__device__ __forceinline__ void upk2(unsigned long long v, float& a, float& b) {
    asm("mov.b64 {%0,%1},%2;" : "=f"(a), "=f"(b) : "l"(v));
}
__device__ __forceinline__ void ffma2(unsigned long long& d, unsigned long long a,
                                      unsigned long long b) {
    asm("fma.rn.f32x2 %0,%1,%2,%0;" : "+l"(d) : "l"(a), "l"(b));
}

// ======== CSR build ========
__global__ void k_deg_init(int* deg) {
    int i = blockIdx.x * blockDim.x + threadIdx.x;
    if (i < NN) deg[i] = 1;                    // self loop
}
__global__ void k_deg_count(const int* __restrict__ dst, int* deg) {
    int t0 = blockIdx.x * 1024 + threadIdx.x;
#pragma unroll
    for (int j = 0; j < 4; j++) {
        int i = t0 + j * 256;
        if (i < EE) atomicAdd(&deg[dst[i]], 1);
    }
}
__global__ void k_blocksum(const int* __restrict__ deg, int* __restrict__ bsum) {
    __shared__ int s[256];
    int t = threadIdx.x;
    int i = blockIdx.x * 256 + t;
    s[t] = (i < NN) ? deg[i] : 0;
    __syncthreads();
    for (int o = 128; o; o >>= 1) {
        if (t < o) s[t] += s[t + o];
        __syncthreads();
    }
    if (t == 0) bsum[blockIdx.x] = s[0];
}
__global__ void k_scanb(const int* __restrict__ bsum, int* __restrict__ bbase) {
    __shared__ int s[512];
    int t = threadIdx.x;
    int v = (t < NB) ? bsum[t] : 0;
    s[t] = v;
    __syncthreads();
    for (int off = 1; off < 512; off <<= 1) {
        int u = (t >= off) ? s[t - off] : 0;
        __syncthreads();
        s[t] += u;
        __syncthreads();
    }
    if (t < NB) bbase[t] = s[t] - v;
}
__global__ void k_rpfill(const int* __restrict__ deg, const int* __restrict__ bbase,
                         int* __restrict__ rp, int* __restrict__ cur,
                         float* __restrict__ dinv) {
    __shared__ int s[256];
    int t = threadIdx.x;
    int i = blockIdx.x * 256 + t;
    int v = (i < NN) ? deg[i] : 0;
    s[t] = v;
    __syncthreads();
    for (int off = 1; off < 256; off <<= 1) {
        int u = (t >= off) ? s[t - off] : 0;
        __syncthreads();
        s[t] += u;
        __syncthreads();
    }
    if (i < NN) {
        int ex = bbase[blockIdx.x] + s[t] - v;   // exclusive prefix
        rp[i] = ex;
        cur[i] = ex;
        dinv[i] = rsqrtf((float)v);
    }
    if (i == 0) rp[NN] = ET;
}
__global__ void k_csr_fill(const int* __restrict__ src, const int* __restrict__ dst,
                           int* __restrict__ cur, int* __restrict__ csr) {
    int t0 = blockIdx.x * 1024 + threadIdx.x;
#pragma unroll
    for (int j = 0; j < 4; j++) {
        int i = t0 + j * 256;
        if (i < ET) {
            int s, d;
            if (i < EE) { s = src[i]; d = dst[i]; } else { s = d = i - EE; }
            int pos = atomicAdd(&cur[d], 1);
            csr[pos] = s;
        }
    }
}

// ======== GEMM: C[M,64] = A[M,K] @ W[K,64], f32x2 packed, 128-row blocks ========
template <int K>
__global__ void k_gemm2(const float* __restrict__ A, const float* __restrict__ W,
                        float* __restrict__ C, int M) {
    extern __shared__ float sm[];
    float* Ws = sm;                 // K*64
    float* Xs = sm + K * 64;        // K*132 (transposed, padded for float4)
    int tid = threadIdx.x;
    for (int idx = tid; idx < K * 64; idx += 256) Ws[idx] = W[idx];
    int base = blockIdx.x * 128;
    for (int idx = tid; idx < 128 * K; idx += 256) {
        int n = idx / K, k = idx - n * K;
        int row = base + n;
        Xs[k * 132 + n] = (row < M) ? A[row * K + k] : 0.f;
    }
    __syncthreads();
    int c0 = (tid & 7) * 8;
    int n0 = (tid >> 3) * 4;
    unsigned long long acc[4][4];
#pragma unroll
    for (int r = 0; r < 4; r++)
#pragma unroll
        for (int c = 0; c < 4; c++) acc[r][c] = 0ull;
#pragma unroll 8
    for (int k = 0; k < K; k++) {
        float4 w0 = *(const float4*)&Ws[k * 64 + c0];
        float4 w1 = *(const float4*)&Ws[k * 64 + c0 + 4];
        float4 xv = *(const float4*)&Xs[k * 132 + n0];
        unsigned long long wp0 = pk2(w0.x, w0.y), wp1 = pk2(w0.z, w0.w);
        unsigned long long wp2 = pk2(w1.x, w1.y), wp3 = pk2(w1.z, w1.w);
        unsigned long long x0 = pk2(xv.x, xv.x), x1 = pk2(xv.y, xv.y);
        unsigned long long x2 = pk2(xv.z, xv.z), x3 = pk2(xv.w, xv.w);
        ffma2(acc[0][0], x0, wp0); ffma2(acc[0][1], x0, wp1);
        ffma2(acc[0][2], x0, wp2); ffma2(acc[0][3], x0, wp3);
        ffma2(acc[1][0], x1, wp0); ffma2(acc[1][1], x1, wp1);
        ffma2(acc[1][2], x1, wp2); ffma2(acc[1][3], x1, wp3);
        ffma2(acc[2][0], x2, wp0); ffma2(acc[2][1], x2, wp1);
        ffma2(acc[2][2], x2, wp2); ffma2(acc[2][3], x2, wp3);
        ffma2(acc[3][0], x3, wp0); ffma2(acc[3][1], x3, wp1);
        ffma2(acc[3][2], x3, wp2); ffma2(acc[3][3], x3, wp3);
    }
#pragma unroll
    for (int r = 0; r < 4; r++) {
        int row = base + n0 + r;
        if (row < M) {
            float4 o0, o1;
            upk2(acc[r][0], o0.x, o0.y); upk2(acc[r][1], o0.z, o0.w);
            upk2(acc[r][2], o1.x, o1.y); upk2(acc[r][3], o1.z, o1.w);
            *(float4*)&C[row * 64 + c0]     = o0;
            *(float4*)&C[row * 64 + c0 + 4] = o1;
        }
    }
}

// ======== GCN aggregation: warp per node, half-warp per edge, float4 ========
__global__ void k_gcn_agg(const float* __restrict__ h, const int* __restrict__ rp,
                          const int* __restrict__ csr, const float* __restrict__ dinv,
                          const float* __restrict__ b, float* __restrict__ act) {
    int node = blockIdx.x * 8 + (threadIdx.x >> 5);
    if (node >= NN) return;
    int lane = threadIdx.x & 31;
    int half = lane >> 4;
    int fi = (lane & 15) * 4;
    int e = rp[node], end = rp[node + 1];
    float dd = dinv[node];
    float ax = 0.f, ay = 0.f, az = 0.f, aw = 0.f;
    for (; e + 4 <= end; e += 4) {
        int sA = csr[e + half], sB = csr[e + 2 + half];
        float mA = dinv[sA] * dd, mB = dinv[sB] * dd;
        float4 hA = *(const float4*)&h[sA * 64 + fi];
        float4 hB = *(const float4*)&h[sB * 64 + fi];
        ax = fmaf(hA.x, mA, ax); ay = fmaf(hA.y, mA, ay);
        az = fmaf(hA.z, mA, az); aw = fmaf(hA.w, mA, aw);
        ax = fmaf(hB.x, mB, ax); ay = fmaf(hB.y, mB, ay);
        az = fmaf(hB.z, mB, az); aw = fmaf(hB.w, mB, aw);
    }
    for (; e < end; e += 2) {
        int eA = e + half;
        if (eA < end) {
            int s = csr[eA];
            float m = dinv[s] * dd;
            float4 hv = *(const float4*)&h[s * 64 + fi];
            ax = fmaf(hv.x, m, ax); ay = fmaf(hv.y, m, ay);
            az = fmaf(hv.z, m, az); aw = fmaf(hv.w, m, aw);
        }
    }
    ax += __shfl_xor_sync(0xffffffffu, ax, 16);
    ay += __shfl_xor_sync(0xffffffffu, ay, 16);
    az += __shfl_xor_sync(0xffffffffu, az, 16);
    aw += __shfl_xor_sync(0xffffffffu, aw, 16);
    if (half == 0) {
        float4 bv = *(const float4*)&b[fi];
        float4 o = make_float4(fmaxf(ax + bv.x, 0.f), fmaxf(ay + bv.y, 0.f),
                               fmaxf(az + bv.z, 0.f), fmaxf(aw + bv.w, 0.f));
        *(float4*)&act[node * 64 + fi] = o;
    }
}

// ======== GAT node attention coefficients ========
__global__ void k_alpha(const float* __restrict__ h, const float* __restrict__ avs,
                        const float* __restrict__ avd, float* __restrict__ as_out,
                        float* __restrict__ ad_out, int n) {
    int warp = (blockIdx.x * blockDim.x + threadIdx.x) >> 5;
    int lane = threadIdx.x & 31;
    if (warp >= n) return;
    float h0 = h[warp * 64 + lane], h1 = h[warp * 64 + 32 + lane];
    float s = h0 * avs[lane] + h1 * avs[lane + 32];
    float d = h0 * avd[lane] + h1 * avd[lane + 32];
#pragma unroll
    for (int o = 16; o; o >>= 1) {
        s += __shfl_down_sync(0xffffffffu, s, o);
        d += __shfl_down_sync(0xffffffffu, d, o);
    }
    if (lane == 0) { as_out[warp] = s; ad_out[warp] = d; }
}

__device__ __forceinline__ float lrelu(float v) { return v >= 0.f ? v : 0.2f * v; }

// ======== fused GAT aggregation ========
__global__ void k_gat_agg(const float* __restrict__ h, const int* __restrict__ rp,
                          const int* __restrict__ csr, const float* __restrict__ as_,
                          const float* __restrict__ ad_, const float* __restrict__ b,
                          float* __restrict__ act) {
    int node = blockIdx.x * 8 + (threadIdx.x >> 5);
    if (node >= NN) return;
    int lane = threadIdx.x & 31;
    int half = lane >> 4;
    int fi = (lane & 15) * 4;
    int begin = rp[node], end = rp[node + 1];
    float adv = ad_[node];

    // pass 1: max (lanes strided over edges)
    float mx = -1e30f;
    for (int e = begin + lane; e < end; e += 32)
        mx = fmaxf(mx, lrelu(as_[csr[e]] + adv));
#pragma unroll
    for (int o = 16; o; o >>= 1) mx = fmaxf(mx, __shfl_xor_sync(0xffffffffu, mx, o));

    // pass 2: denom
    float smv = 0.f;
    for (int e = begin + lane; e < end; e += 32)
        smv += __expf(lrelu(as_[csr[e]] + adv) - mx);
#pragma unroll
    for (int o = 16; o; o >>= 1) smv += __shfl_xor_sync(0xffffffffu, smv, o);
    float inv = 1.f / smv;

    // pass 3: weighted feature gather, half-warp per edge
    float ax = 0.f, ay = 0.f, az = 0.f, aw = 0.f;
    int e = begin;
    for (; e + 4 <= end; e += 4) {
        int sA = csr[e + half], sB = csr[e + 2 + half];
        float alA = __expf(lrelu(as_[sA] + adv) - mx) * inv;
        float alB = __expf(lrelu(as_[sB] + adv) - mx) * inv;
        float4 hA = *(const float4*)&h[sA * 64 + fi];
        float4 hB = *(const float4*)&h[sB * 64 + fi];
        ax = fmaf(hA.x, alA, ax); ay = fmaf(hA.y, alA, ay);
        az = fmaf(hA.z, alA, az); aw = fmaf(hA.w, alA, aw);
        ax = fmaf(hB.x, alB, ax); ay = fmaf(hB.y, alB, ay);
        az = fmaf(hB.z, alB, az); aw = fmaf(hB.w, alB, aw);
    }
    for (; e < end; e += 2) {
        int eA = e + half;
        if (eA < end) {
            int s = csr[eA];
            float al = __expf(lrelu(as_[s] + adv) - mx) * inv;
            float4 hv = *(const float4*)&h[s * 64 + fi];
            ax = fmaf(hv.x, al, ax); ay = fmaf(hv.y, al, ay);
            az = fmaf(hv.z, al, az); aw = fmaf(hv.w, al, aw);
        }
    }
    ax += __shfl_xor_sync(0xffffffffu, ax, 16);
    ay += __shfl_xor_sync(0xffffffffu, ay, 16);
    az += __shfl_xor_sync(0xffffffffu, az, 16);
    aw += __shfl_xor_sync(0xffffffffu, aw, 16);
    if (half == 0) {
        float4 bv = *(const float4*)&b[fi];
        float4 o = make_float4(fmaxf(ax + bv.x, 0.f), fmaxf(ay + bv.y, 0.f),
                               fmaxf(az + bv.z, 0.f), fmaxf(aw + bv.w, 0.f));
        *(float4*)&act[node * 64 + fi] = o;
    }
}

// ======== heads + fused graph-embedding partial sums ========
__global__ void k_heads(const float* __restrict__ h,
                        const float* __restrict__ Wopt, const float* __restrict__ bopt,
                        const float* __restrict__ Wb1, const float* __restrict__ bb1,
                        const float* __restrict__ Wb2, const float* __restrict__ bb2,
                        float* __restrict__ out, float* __restrict__ emb, int n) {
    __shared__ float sWopt[640], sbopt[10], sWb1[2048], sbb1[32], sWb2[32];
    __shared__ float hrow[8][64];
    int tid = threadIdx.x;
    for (int i = tid; i < 640; i += 256) sWopt[i] = Wopt[i];
    for (int i = tid; i < 2048; i += 256) sWb1[i] = Wb1[i];
    if (tid < 10) sbopt[tid] = bopt[tid];
    if (tid < 32) { sbb1[tid] = bb1[tid]; sWb2[tid] = Wb2[tid]; }
    __syncthreads();
    float bb2v = bb2[0];
    int warp = tid >> 5, lane = tid & 31;
    float p0 = 0.f, p1 = 0.f;   // per-lane graph-embedding partials
    for (int node = blockIdx.x * 8 + warp; node < n; node += gridDim.x * 8) {
        float h0 = h[node * 64 + lane];
        float h1 = h[node * 64 + 32 + lane];
        hrow[warp][lane] = h0;
        hrow[warp][lane + 32] = h1;
        p0 += h0; p1 += h1;
        __syncwarp();
        if (lane < CC) {
            float acc = sbopt[lane];
#pragma unroll
            for (int k = 0; k < 64; k++) acc += hrow[warp][k] * sWopt[k * CC + lane];
            out[node * CC + lane] = acc;
        }
        float t = sbb1[lane];
#pragma unroll
        for (int k = 0; k < 64; k++) t += hrow[warp][k] * sWb1[k * 32 + lane];
        t = fmaxf(t, 0.f) * sWb2[lane];
#pragma unroll
        for (int o = 16; o; o >>= 1) t += __shfl_down_sync(0xffffffffu, t, o);
        if (lane == 0) out[NN * CC + node] = 1.f / (1.f + __expf(-(t + bb2v)));
        __syncwarp();
    }
    atomicAdd(&emb[lane], p0);
    atomicAdd(&emb[lane + 32], p1);
}

__global__ void k_fill(float* p, float v, int n) {
    int i = blockIdx.x * blockDim.x + threadIdx.x;
    if (i < n) p[i] = v;
}
__global__ void k_finish(const float* __restrict__ emb, float* __restrict__ out) {
    int t = threadIdx.x;
    if (t < 64) out[NN * CC + NN + t] = emb[t] * (1.0f / NN);
}

// ======== launch ========
extern "C" void kernel_launch(void* const* d_in, const int* in_sizes, int n_in,
                              void* d_out, int out_size) {
    const float* x    = (const float*)d_in[0];
    const int*   ei   = (const int*)d_in[1];
    const int*   src  = ei;
    const int*   dst  = ei + EE;
    const float* W1   = (const float*)d_in[2];
    const float* b1   = (const float*)d_in[3];
    const float* W2   = (const float*)d_in[4];
    const float* a_s  = (const float*)d_in[5];
    const float* a_d  = (const float*)d_in[6];
    const float* b2   = (const float*)d_in[7];
    const float* W3   = (const float*)d_in[8];
    const float* b3   = (const float*)d_in[9];
    const float* Wopt = (const float*)d_in[10];
    const float* bopt = (const float*)d_in[11];
    const float* Wb1  = (const float*)d_in[12];
    const float* bb1  = (const float*)d_in[13];
    const float* Wb2  = (const float*)d_in[14];
    const float* bb2  = (const float*)d_in[15];
    float* out = (float*)d_out;

    float *pLin, *pAct, *pDinv, *pAs, *pAd, *pEmb;
    int *pDeg, *pRp, *pCur, *pCsr, *pBsum, *pBbase;
    cudaGetSymbolAddress((void**)&pLin,  g_lin);
    cudaGetSymbolAddress((void**)&pAct,  g_act);
    cudaGetSymbolAddress((void**)&pDeg,  g_deg);
    cudaGetSymbolAddress((void**)&pRp,   g_rowptr);
    cudaGetSymbolAddress((void**)&pCur,  g_cursor);
    cudaGetSymbolAddress((void**)&pCsr,  g_csr);
    cudaGetSymbolAddress((void**)&pBsum, g_bsum);
    cudaGetSymbolAddress((void**)&pBbase,g_bbase);
    cudaGetSymbolAddress((void**)&pDinv, g_dinv);
    cudaGetSymbolAddress((void**)&pAs,   g_as);
    cudaGetSymbolAddress((void**)&pAd,   g_ad);
    cudaGetSymbolAddress((void**)&pEmb,  g_emb);

    const int TB = 256;
    const int nBlkW  = (NN * 32 + TB - 1) / TB;    // warp per node
    const int nBlkA  = (NN + 7) / 8;
    const int nBlkG  = (NN + 127) / 128;           // 782
    const int smem32 = 32 * (64 + 132) * 4;        // 25088
    const int smem64 = 64 * (64 + 132) * 4;        // 50176

    static int attr_done = 0;
    if (!attr_done) {
        cudaFuncSetAttribute(k_gemm2<64>, cudaFuncAttributeMaxDynamicSharedMemorySize, smem64);
        cudaFuncSetAttribute(k_gemm2<32>, cudaFuncAttributeMaxDynamicSharedMemorySize, smem32);
        attr_done = 1;
    }

    // ---- CSR build ----
    k_deg_init<<<NB, TB>>>(pDeg);
    k_deg_count<<<(EE + 1023) / 1024, TB>>>(dst, pDeg);
    k_blocksum<<<NB, TB>>>(pDeg, pBsum);
    k_scanb<<<1, 512>>>(pBsum, pBbase);
    k_rpfill<<<NB, TB>>>(pDeg, pBbase, pRp, pCur, pDinv);
    k_csr_fill<<<(ET + 1023) / 1024, TB>>>(src, dst, pCur, pCsr);

    // ---- GCN layer 1 ----
    k_gemm2<32><<<nBlkG, TB, smem32>>>(x, W1, pLin, NN);
    k_gcn_agg<<<nBlkA, TB>>>(pLin, pRp, pCsr, pDinv, b1, pAct);

    // ---- GAT layer ----
    k_gemm2<64><<<nBlkG, TB, smem64>>>(pAct, W2, pLin, NN);
    k_alpha<<<nBlkW, TB>>>(pLin, a_s, a_d, pAs, pAd, NN);
    k_gat_agg<<<nBlkA, TB>>>(pLin, pRp, pCsr, pAs, pAd, b2, pAct);

    // ---- GCN layer 3 ----
    k_gemm2<64><<<nBlkG, TB, smem64>>>(pAct, W3, pLin, NN);
    k_gcn_agg<<<nBlkA, TB>>>(pLin, pRp, pCsr, pDinv, b3, pAct);

    // ---- heads + embedding ----
    k_fill<<<1, 64>>>(pEmb, 0.f, 64);
    k_heads<<<1184, TB>>>(pAct, Wopt, bopt, Wb1, bb1, Wb2, bb2, out, pEmb, NN);
    k_finish<<<1, 64>>>(pEmb, out);
}

// round 6
// speedup vs baseline: 1.9187x; 1.2233x over previous
#include <cuda_runtime.h>
#include <cuda_bf16.h>
#include <cuda_fp16.h>
#include <math.h>

#define NN 100000
#define EE 1250000
#define ET (NN + EE)          // edges + self loops
#define CC 10
#define NB 391                // ceil(NN/256)

// -------- scratch (no allocations allowed) --------
__device__ __half g_lin[NN * 64];    // fp16 packed features for gathers
__device__ float g_act[NN * 64];     // fp32 aggregated activations
__device__ int   g_deg[NN];
__device__ int   g_rowptr[NN + 1];
__device__ int   g_cursor[NN];
__device__ int   g_csr[ET];
__device__ int   g_bsum[512];
__device__ int   g_bbase[512];
__device__ float g_dinv[NN];
__device__ float g_as[NN];
__device__ float g_ad[NN];
__device__ float g_emb[64];

// ======== f32x2 packed math helpers (sm_103a FFMA2) ========
__device__ __forceinline__ unsigned long long pk2(float a, float b) {
    unsigned long long r;
    asm("mov.b64 %0,{%1,%2};" : "=l"(r) : "f"(a), "f"(b));
    return r;
}
__device__ __forceinline__ void upk2(unsigned long long v, float& a, float& b) {
    asm("mov.b64 {%0,%1},%2;" : "=f"(a), "=f"(b) : "l"(v));
}
__device__ __forceinline__ void ffma2(unsigned long long& d, unsigned long long a,
                                      unsigned long long b) {
    asm("fma.rn.f32x2 %0,%1,%2,%0;" : "+l"(d) : "l"(a), "l"(b));
}

// ======== CSR build ========
__global__ void k_deg_init(int* deg) {
    int i = blockIdx.x * blockDim.x + threadIdx.x;
    if (i < NN) deg[i] = 1;                    // self loop
}
__global__ void k_deg_count(const int* __restrict__ dst, int* deg) {
    int t0 = blockIdx.x * 1024 + threadIdx.x;
#pragma unroll
    for (int j = 0; j < 4; j++) {
        int i = t0 + j * 256;
        if (i < EE) atomicAdd(&deg[dst[i]], 1);
    }
}
__global__ void k_blocksum(const int* __restrict__ deg, int* __restrict__ bsum) {
    __shared__ int s[256];
    int t = threadIdx.x;
    int i = blockIdx.x * 256 + t;
    s[t] = (i < NN) ? deg[i] : 0;
    __syncthreads();
    for (int o = 128; o; o >>= 1) {
        if (t < o) s[t] += s[t + o];
        __syncthreads();
    }
    if (t == 0) bsum[blockIdx.x] = s[0];
}
__global__ void k_scanb(const int* __restrict__ bsum, int* __restrict__ bbase) {
    __shared__ int s[512];
    int t = threadIdx.x;
    int v = (t < NB) ? bsum[t] : 0;
    s[t] = v;
    __syncthreads();
    for (int off = 1; off < 512; off <<= 1) {
        int u = (t >= off) ? s[t - off] : 0;
        __syncthreads();
        s[t] += u;
        __syncthreads();
    }
    if (t < NB) bbase[t] = s[t] - v;
}
__global__ void k_rpfill(const int* __restrict__ deg, const int* __restrict__ bbase,
                         int* __restrict__ rp, int* __restrict__ cur,
                         float* __restrict__ dinv) {
    __shared__ int s[256];
    int t = threadIdx.x;
    int i = blockIdx.x * 256 + t;
    int v = (i < NN) ? deg[i] : 0;
    s[t] = v;
    __syncthreads();
    for (int off = 1; off < 256; off <<= 1) {
        int u = (t >= off) ? s[t - off] : 0;
        __syncthreads();
        s[t] += u;
        __syncthreads();
    }
    if (i < NN) {
        int ex = bbase[blockIdx.x] + s[t] - v;
        rp[i] = ex;
        cur[i] = ex;
        dinv[i] = rsqrtf((float)v);
    }
    if (i == 0) rp[NN] = ET;
}
__global__ void k_csr_fill(const int* __restrict__ src, const int* __restrict__ dst,
                           int* __restrict__ cur, int* __restrict__ csr) {
    int t0 = blockIdx.x * 1024 + threadIdx.x;
#pragma unroll
    for (int j = 0; j < 4; j++) {
        int i = t0 + j * 256;
        if (i < ET) {
            int s, d;
            if (i < EE) { s = src[i]; d = dst[i]; } else { s = d = i - EE; }
            int pos = atomicAdd(&cur[d], 1);
            csr[pos] = s;
        }
    }
}

// ======== GEMM: C_h[M,64] = A[M,K] @ W[K,64] (half output), optional fused alpha ========
template <int K, bool ALPHA>
__global__ void k_gemm2(const float* __restrict__ A, const float* __restrict__ W,
                        __half* __restrict__ C,
                        const float* __restrict__ avs, const float* __restrict__ avd,
                        float* __restrict__ as_out, float* __restrict__ ad_out, int M) {
    extern __shared__ float sm[];
    float* Ws = sm;                 // K*64
    float* Xs = sm + K * 64;        // K*132 (transposed, padded)
    int tid = threadIdx.x;
    for (int idx = tid; idx < K * 64; idx += 256) Ws[idx] = W[idx];
    int base = blockIdx.x * 128;
    for (int idx = tid; idx < 128 * K; idx += 256) {
        int n = idx / K, k = idx - n * K;
        int row = base + n;
        Xs[k * 132 + n] = (row < M) ? A[row * K + k] : 0.f;
    }
    __syncthreads();
    int c0 = (tid & 7) * 8;
    int n0 = (tid >> 3) * 4;
    unsigned long long acc[4][4];
#pragma unroll
    for (int r = 0; r < 4; r++)
#pragma unroll
        for (int c = 0; c < 4; c++) acc[r][c] = 0ull;
#pragma unroll 8
    for (int k = 0; k < K; k++) {
        float4 w0 = *(const float4*)&Ws[k * 64 + c0];
        float4 w1 = *(const float4*)&Ws[k * 64 + c0 + 4];
        float4 xv = *(const float4*)&Xs[k * 132 + n0];
        unsigned long long wp0 = pk2(w0.x, w0.y), wp1 = pk2(w0.z, w0.w);
        unsigned long long wp2 = pk2(w1.x, w1.y), wp3 = pk2(w1.z, w1.w);
        unsigned long long x0 = pk2(xv.x, xv.x), x1 = pk2(xv.y, xv.y);
        unsigned long long x2 = pk2(xv.z, xv.z), x3 = pk2(xv.w, xv.w);
        ffma2(acc[0][0], x0, wp0); ffma2(acc[0][1], x0, wp1);
        ffma2(acc[0][2], x0, wp2); ffma2(acc[0][3], x0, wp3);
        ffma2(acc[1][0], x1, wp0); ffma2(acc[1][1], x1, wp1);
        ffma2(acc[1][2], x1, wp2); ffma2(acc[1][3], x1, wp3);
        ffma2(acc[2][0], x2, wp0); ffma2(acc[2][1], x2, wp1);
        ffma2(acc[2][2], x2, wp2); ffma2(acc[2][3], x2, wp3);
        ffma2(acc[3][0], x3, wp0); ffma2(acc[3][1], x3, wp1);
        ffma2(acc[3][2], x3, wp2); ffma2(acc[3][3], x3, wp3);
    }
    float sav[8], dav[8];
    if (ALPHA) {
#pragma unroll
        for (int j = 0; j < 8; j++) { sav[j] = avs[c0 + j]; dav[j] = avd[c0 + j]; }
    }
#pragma unroll
    for (int r = 0; r < 4; r++) {
        int row = base + n0 + r;
        float f[8];
        upk2(acc[r][0], f[0], f[1]); upk2(acc[r][1], f[2], f[3]);
        upk2(acc[r][2], f[4], f[5]); upk2(acc[r][3], f[6], f[7]);
        if (row < M) {
            __half2 hh[4];
#pragma unroll
            for (int j = 0; j < 4; j++)
                hh[j] = __float22half2_rn(make_float2(f[2 * j], f[2 * j + 1]));
            *(uint4*)&C[row * 64 + c0] = *(uint4*)hh;
        }
        if (ALPHA) {
            float sp = 0.f, dp = 0.f;
#pragma unroll
            for (int j = 0; j < 8; j++) { sp = fmaf(f[j], sav[j], sp); dp = fmaf(f[j], dav[j], dp); }
#pragma unroll
            for (int o = 1; o < 8; o <<= 1) {
                sp += __shfl_xor_sync(0xffffffffu, sp, o);
                dp += __shfl_xor_sync(0xffffffffu, dp, o);
            }
            if ((tid & 7) == 0 && row < M) { as_out[row] = sp; ad_out[row] = dp; }
        }
    }
}

// ======== half gather helper: lane q holds features 4q..4q+3 ========
__device__ __forceinline__ void hacc(const uint2* __restrict__ hp, int s, int q, float m,
                                     float& ax, float& ay, float& az, float& aw) {
    uint2 rv = hp[(unsigned)s * 16 + q];
    float2 f0 = __half22float2(*(__half2*)&rv.x);
    float2 f1 = __half22float2(*(__half2*)&rv.y);
    ax = fmaf(f0.x, m, ax); ay = fmaf(f0.y, m, ay);
    az = fmaf(f1.x, m, az); aw = fmaf(f1.y, m, aw);
}

// ======== GCN aggregation: warp/node, half-warp/edge, 8-edge unroll ========
__global__ void k_gcn_agg(const __half* __restrict__ h, const int* __restrict__ rp,
                          const int* __restrict__ csr, const float* __restrict__ dinv,
                          const float* __restrict__ b, float* __restrict__ act) {
    int node = blockIdx.x * 8 + (threadIdx.x >> 5);
    if (node >= NN) return;
    int lane = threadIdx.x & 31;
    int half = lane >> 4;
    int q = lane & 15;
    const uint2* hp = (const uint2*)h;
    int e = rp[node], end = rp[node + 1];
    float dd = dinv[node];
    float ax = 0.f, ay = 0.f, az = 0.f, aw = 0.f;
    for (; e + 8 <= end; e += 8) {
        int s0 = csr[e + half],     s1 = csr[e + 2 + half];
        int s2 = csr[e + 4 + half], s3 = csr[e + 6 + half];
        float m0 = dinv[s0] * dd, m1 = dinv[s1] * dd;
        float m2 = dinv[s2] * dd, m3 = dinv[s3] * dd;
        hacc(hp, s0, q, m0, ax, ay, az, aw);
        hacc(hp, s1, q, m1, ax, ay, az, aw);
        hacc(hp, s2, q, m2, ax, ay, az, aw);
        hacc(hp, s3, q, m3, ax, ay, az, aw);
    }
    for (; e < end; e += 2) {
        int eA = e + half;
        if (eA < end) {
            int s = csr[eA];
            hacc(hp, s, q, dinv[s] * dd, ax, ay, az, aw);
        }
    }
    ax += __shfl_xor_sync(0xffffffffu, ax, 16);
    ay += __shfl_xor_sync(0xffffffffu, ay, 16);
    az += __shfl_xor_sync(0xffffffffu, az, 16);
    aw += __shfl_xor_sync(0xffffffffu, aw, 16);
    if (half == 0) {
        int fi = q * 4;
        float4 bv = *(const float4*)&b[fi];
        float4 o = make_float4(fmaxf(ax + bv.x, 0.f), fmaxf(ay + bv.y, 0.f),
                               fmaxf(az + bv.z, 0.f), fmaxf(aw + bv.w, 0.f));
        *(float4*)&act[node * 64 + fi] = o;
    }
}

__device__ __forceinline__ float lrelu(float v) { return v >= 0.f ? v : 0.2f * v; }

// ======== fused GAT aggregation ========
__global__ void k_gat_agg(const __half* __restrict__ h, const int* __restrict__ rp,
                          const int* __restrict__ csr, const float* __restrict__ as_,
                          const float* __restrict__ ad_, const float* __restrict__ b,
                          float* __restrict__ act) {
    int node = blockIdx.x * 8 + (threadIdx.x >> 5);
    if (node >= NN) return;
    int lane = threadIdx.x & 31;
    int half = lane >> 4;
    int q = lane & 15;
    const uint2* hp = (const uint2*)h;
    int begin = rp[node], end = rp[node + 1];
    float adv = ad_[node];

    float mx = -1e30f;
    for (int e = begin + lane; e < end; e += 32)
        mx = fmaxf(mx, lrelu(as_[csr[e]] + adv));
#pragma unroll
    for (int o = 16; o; o >>= 1) mx = fmaxf(mx, __shfl_xor_sync(0xffffffffu, mx, o));

    float smv = 0.f;
    for (int e = begin + lane; e < end; e += 32)
        smv += __expf(lrelu(as_[csr[e]] + adv) - mx);
#pragma unroll
    for (int o = 16; o; o >>= 1) smv += __shfl_xor_sync(0xffffffffu, smv, o);
    float inv = 1.f / smv;

    float ax = 0.f, ay = 0.f, az = 0.f, aw = 0.f;
    int e = begin;
    for (; e + 8 <= end; e += 8) {
        int s0 = csr[e + half],     s1 = csr[e + 2 + half];
        int s2 = csr[e + 4 + half], s3 = csr[e + 6 + half];
        float a0 = __expf(lrelu(as_[s0] + adv) - mx) * inv;
        float a1 = __expf(lrelu(as_[s1] + adv) - mx) * inv;
        float a2 = __expf(lrelu(as_[s2] + adv) - mx) * inv;
        float a3 = __expf(lrelu(as_[s3] + adv) - mx) * inv;
        hacc(hp, s0, q, a0, ax, ay, az, aw);
        hacc(hp, s1, q, a1, ax, ay, az, aw);
        hacc(hp, s2, q, a2, ax, ay, az, aw);
        hacc(hp, s3, q, a3, ax, ay, az, aw);
    }
    for (; e < end; e += 2) {
        int eA = e + half;
        if (eA < end) {
            int s = csr[eA];
            float al = __expf(lrelu(as_[s] + adv) - mx) * inv;
            hacc(hp, s, q, al, ax, ay, az, aw);
        }
    }
    ax += __shfl_xor_sync(0xffffffffu, ax, 16);
    ay += __shfl_xor_sync(0xffffffffu, ay, 16);
    az += __shfl_xor_sync(0xffffffffu, az, 16);
    aw += __shfl_xor_sync(0xffffffffu, aw, 16);
    if (half == 0) {
        int fi = q * 4;
        float4 bv = *(const float4*)&b[fi];
        float4 o = make_float4(fmaxf(ax + bv.x, 0.f), fmaxf(ay + bv.y, 0.f),
                               fmaxf(az + bv.z, 0.f), fmaxf(aw + bv.w, 0.f));
        *(float4*)&act[node * 64 + fi] = o;
    }
}

// ======== heads + fused graph-embedding partials (Wb1 in registers) ========
__global__ void k_heads(const float* __restrict__ h,
                        const float* __restrict__ Wopt, const float* __restrict__ bopt,
                        const float* __restrict__ Wb1, const float* __restrict__ bb1,
                        const float* __restrict__ Wb2, const float* __restrict__ bb2,
                        float* __restrict__ out, float* __restrict__ emb, int n) {
    __shared__ float sWopt[640], sbopt[10], sbb1[32], sWb2[32];
    __shared__ float hrow[8][64];
    int tid = threadIdx.x;
    for (int i = tid; i < 640; i += 256) sWopt[i] = Wopt[i];
    if (tid < 10) sbopt[tid] = bopt[tid];
    if (tid < 32) { sbb1[tid] = bb1[tid]; sWb2[tid] = Wb2[tid]; }
    __syncthreads();
    float bb2v = bb2[0];
    int warp = tid >> 5, lane = tid & 31;
    float wb1r[64];
#pragma unroll
    for (int k = 0; k < 64; k++) wb1r[k] = Wb1[k * 32 + lane];
    float p0 = 0.f, p1 = 0.f;
    bool opt_lane = lane < CC;
    for (int node = blockIdx.x * 8 + warp; node < n; node += gridDim.x * 8) {
        float h0 = h[node * 64 + lane];
        float h1 = h[node * 64 + 32 + lane];
        hrow[warp][lane] = h0;
        hrow[warp][lane + 32] = h1;
        p0 += h0; p1 += h1;
        __syncwarp();
        float t = sbb1[lane];
        float acc = opt_lane ? sbopt[lane] : 0.f;
#pragma unroll
        for (int k = 0; k < 64; k++) {
            float hk = hrow[warp][k];
            t = fmaf(hk, wb1r[k], t);
            if (opt_lane) acc = fmaf(hk, sWopt[k * CC + lane], acc);
        }
        if (opt_lane) out[node * CC + lane] = acc;
        t = fmaxf(t, 0.f) * sWb2[lane];
#pragma unroll
        for (int o = 16; o; o >>= 1) t += __shfl_down_sync(0xffffffffu, t, o);
        if (lane == 0) out[NN * CC + node] = 1.f / (1.f + __expf(-(t + bb2v)));
        __syncwarp();
    }
    atomicAdd(&emb[lane], p0);
    atomicAdd(&emb[lane + 32], p1);
}

__global__ void k_fill(float* p, float v, int n) {
    int i = blockIdx.x * blockDim.x + threadIdx.x;
    if (i < n) p[i] = v;
}
__global__ void k_finish(const float* __restrict__ emb, float* __restrict__ out) {
    int t = threadIdx.x;
    if (t < 64) out[NN * CC + NN + t] = emb[t] * (1.0f / NN);
}

// ======== launch ========
extern "C" void kernel_launch(void* const* d_in, const int* in_sizes, int n_in,
                              void* d_out, int out_size) {
    const float* x    = (const float*)d_in[0];
    const int*   ei   = (const int*)d_in[1];
    const int*   src  = ei;
    const int*   dst  = ei + EE;
    const float* W1   = (const float*)d_in[2];
    const float* b1   = (const float*)d_in[3];
    const float* W2   = (const float*)d_in[4];
    const float* a_s  = (const float*)d_in[5];
    const float* a_d  = (const float*)d_in[6];
    const float* b2   = (const float*)d_in[7];
    const float* W3   = (const float*)d_in[8];
    const float* b3   = (const float*)d_in[9];
    const float* Wopt = (const float*)d_in[10];
    const float* bopt = (const float*)d_in[11];
    const float* Wb1  = (const float*)d_in[12];
    const float* bb1  = (const float*)d_in[13];
    const float* Wb2  = (const float*)d_in[14];
    const float* bb2  = (const float*)d_in[15];
    float* out = (float*)d_out;

    __half* pLin;
    float *pAct, *pDinv, *pAs, *pAd, *pEmb;
    int *pDeg, *pRp, *pCur, *pCsr, *pBsum, *pBbase;
    cudaGetSymbolAddress((void**)&pLin,  g_lin);
    cudaGetSymbolAddress((void**)&pAct,  g_act);
    cudaGetSymbolAddress((void**)&pDeg,  g_deg);
    cudaGetSymbolAddress((void**)&pRp,   g_rowptr);
    cudaGetSymbolAddress((void**)&pCur,  g_cursor);
    cudaGetSymbolAddress((void**)&pCsr,  g_csr);
    cudaGetSymbolAddress((void**)&pBsum, g_bsum);
    cudaGetSymbolAddress((void**)&pBbase,g_bbase);
    cudaGetSymbolAddress((void**)&pDinv, g_dinv);
    cudaGetSymbolAddress((void**)&pAs,   g_as);
    cudaGetSymbolAddress((void**)&pAd,   g_ad);
    cudaGetSymbolAddress((void**)&pEmb,  g_emb);

    const int TB = 256;
    const int nBlkA = (NN + 7) / 8;
    const int nBlkG = (NN + 127) / 128;
    const int smem32 = 32 * (64 + 132) * 4;
    const int smem64 = 64 * (64 + 132) * 4;

    static cudaStream_t s1 = nullptr;
    static cudaEvent_t ev0 = nullptr, ev1 = nullptr;
    static int attr_done = 0;
    if (!attr_done) {
        cudaFuncSetAttribute(k_gemm2<64, true>,  cudaFuncAttributeMaxDynamicSharedMemorySize, smem64);
        cudaFuncSetAttribute(k_gemm2<64, false>, cudaFuncAttributeMaxDynamicSharedMemorySize, smem64);
        cudaFuncSetAttribute(k_gemm2<32, false>, cudaFuncAttributeMaxDynamicSharedMemorySize, smem32);
        cudaStreamCreateWithFlags(&s1, cudaStreamNonBlocking);
        cudaEventCreateWithFlags(&ev0, cudaEventDisableTiming);
        cudaEventCreateWithFlags(&ev1, cudaEventDisableTiming);
        attr_done = 1;
    }

    // ---- fork: CSR build on s1, overlapped with GEMM1 on stream 0 ----
    cudaEventRecord(ev0, 0);
    cudaStreamWaitEvent(s1, ev0, 0);
    k_deg_init<<<NB, TB, 0, s1>>>(pDeg);
    k_deg_count<<<(EE + 1023) / 1024, TB, 0, s1>>>(dst, pDeg);
    k_blocksum<<<NB, TB, 0, s1>>>(pDeg, pBsum);
    k_scanb<<<1, 512, 0, s1>>>(pBsum, pBbase);
    k_rpfill<<<NB, TB, 0, s1>>>(pDeg, pBbase, pRp, pCur, pDinv);
    k_csr_fill<<<(ET + 1023) / 1024, TB, 0, s1>>>(src, dst, pCur, pCsr);
    cudaEventRecord(ev1, s1);

    // ---- GCN layer 1 ----
    k_gemm2<32, false><<<nBlkG, TB, smem32>>>(x, W1, pLin, nullptr, nullptr, nullptr, nullptr, NN);
    cudaStreamWaitEvent(0, ev1, 0);   // join: aggs need CSR + dinv
    k_gcn_agg<<<nBlkA, TB>>>(pLin, pRp, pCsr, pDinv, b1, pAct);

    // ---- GAT layer (alpha fused into GEMM epilogue) ----
    k_gemm2<64, true><<<nBlkG, TB, smem64>>>(pAct, W2, pLin, a_s, a_d, pAs, pAd, NN);
    k_gat_agg<<<nBlkA, TB>>>(pLin, pRp, pCsr, pAs, pAd, b2, pAct);

    // ---- GCN layer 3 ----
    k_gemm2<64, false><<<nBlkG, TB, smem64>>>(pAct, W3, pLin, nullptr, nullptr, nullptr, nullptr, NN);
    k_gcn_agg<<<nBlkA, TB>>>(pLin, pRp, pCsr, pDinv, b3, pAct);

    // ---- heads + embedding ----
    k_fill<<<1, 64>>>(pEmb, 0.f, 64);
    k_heads<<<1184, TB>>>(pAct, Wopt, bopt, Wb1, bb1, Wb2, bb2, out, pEmb, NN);
    k_finish<<<1, 64>>>(pEmb, out);
}